// round 2
// baseline (speedup 1.0000x reference)
#include <cuda_runtime.h>
#include <cuda_bf16.h>
#include <math.h>

// Problem constants
#define BB 2
#define TT 2048
#define CC 1024
#define HH 16
#define DD 64
#define MM (BB*TT)   // 4096

// ---------------------------------------------------------------------------
// Scratch (allocation-free: __device__ globals)
// ---------------------------------------------------------------------------
__device__ float g_q[MM*CC];
__device__ float g_k[MM*CC];
__device__ float g_v[MM*CC];
__device__ float g_att[MM*CC];

// ---------------------------------------------------------------------------
// GEMM:  C[M,N] = A[M,K] @ W[N,K]^T + bias[N]   (torch Linear, NT form)
// 128x128 block tile, BK=16, 256 threads, 8x8 per-thread microtile.
// M,N,K all multiples of tile sizes here (4096/1024/1024) -> no bounds checks.
// ---------------------------------------------------------------------------
#define GBM 128
#define GBN 128
#define GBK 16

__global__ __launch_bounds__(256) void gemm_nt_bias_kernel(
    const float* __restrict__ A, const float* __restrict__ W,
    const float* __restrict__ bias, float* __restrict__ C,
    int M, int N, int K)
{
    __shared__ __align__(16) float As[GBK * GBM];
    __shared__ __align__(16) float Bs[GBK * GBN];

    const int tid = threadIdx.x;
    const int m0 = blockIdx.y * GBM;
    const int n0 = blockIdx.x * GBN;
    const int tx = tid & 15;
    const int ty = tid >> 4;

    float acc[8][8];
    #pragma unroll
    for (int i = 0; i < 8; i++)
        #pragma unroll
        for (int j = 0; j < 8; j++) acc[i][j] = 0.f;

    for (int k0 = 0; k0 < K; k0 += GBK) {
        // Load 128x16 A tile and 128x16 W tile (transposed into [k][m] smem)
        #pragma unroll
        for (int it = 0; it < 2; it++) {
            int vid = tid + it * 256;        // 0..511
            int r   = vid >> 2;              // 0..127
            int c4  = (vid & 3) * 4;         // 0,4,8,12
            float4 a = *reinterpret_cast<const float4*>(
                &A[(size_t)(m0 + r) * K + k0 + c4]);
            As[(c4 + 0) * GBM + r] = a.x;
            As[(c4 + 1) * GBM + r] = a.y;
            As[(c4 + 2) * GBM + r] = a.z;
            As[(c4 + 3) * GBM + r] = a.w;
            float4 b = *reinterpret_cast<const float4*>(
                &W[(size_t)(n0 + r) * K + k0 + c4]);
            Bs[(c4 + 0) * GBN + r] = b.x;
            Bs[(c4 + 1) * GBN + r] = b.y;
            Bs[(c4 + 2) * GBN + r] = b.z;
            Bs[(c4 + 3) * GBN + r] = b.w;
        }
        __syncthreads();

        #pragma unroll
        for (int kk = 0; kk < GBK; kk++) {
            float4 a0 = *reinterpret_cast<const float4*>(&As[kk * GBM + ty * 8]);
            float4 a1 = *reinterpret_cast<const float4*>(&As[kk * GBM + ty * 8 + 4]);
            float4 b0 = *reinterpret_cast<const float4*>(&Bs[kk * GBN + tx * 8]);
            float4 b1 = *reinterpret_cast<const float4*>(&Bs[kk * GBN + tx * 8 + 4]);
            float ra[8] = {a0.x, a0.y, a0.z, a0.w, a1.x, a1.y, a1.z, a1.w};
            float rb[8] = {b0.x, b0.y, b0.z, b0.w, b1.x, b1.y, b1.z, b1.w};
            #pragma unroll
            for (int i = 0; i < 8; i++)
                #pragma unroll
                for (int j = 0; j < 8; j++)
                    acc[i][j] = fmaf(ra[i], rb[j], acc[i][j]);
        }
        __syncthreads();
    }

    // Epilogue: add bias, store
    #pragma unroll
    for (int i = 0; i < 8; i++) {
        size_t row = (size_t)(m0 + ty * 8 + i) * N + n0 + tx * 8;
        #pragma unroll
        for (int j = 0; j < 8; j++)
            C[row + j] = acc[i][j] + bias[n0 + tx * 8 + j];
    }
}

// ---------------------------------------------------------------------------
// Flash attention (causal), fp32.
// grid = (T/64, H, B), 256 threads.
// q/k/v layout: [B, T, H, D] (== reshape of [B,T,C]).
// Each block: 64 query rows, iterate kv tiles of 64 up to the diagonal.
// ---------------------------------------------------------------------------
#define ATM 64              // q rows per block
#define ATN 64              // kv rows per tile
#define LDP 65              // padded row stride in smem

__global__ __launch_bounds__(256) void attention_kernel(
    const float* __restrict__ q, const float* __restrict__ k,
    const float* __restrict__ v, float* __restrict__ o)
{
    extern __shared__ __align__(16) float sm[];
    float* Qs = sm;                    // [64][65]
    float* Ks = Qs + ATM * LDP;        // [64][65]
    float* Vs = Ks + ATN * LDP;        // [64][65]
    float* Ss = Vs + ATN * LDP;        // [64][65]
    float* row_m     = Ss + ATM * LDP; // [64]
    float* row_l     = row_m + ATM;    // [64]
    float* row_alpha = row_l + ATM;    // [64]

    const int tid = threadIdx.x;
    const int qt = blockIdx.x;
    const int h  = blockIdx.y;
    const int b  = blockIdx.z;
    const int q0 = qt * ATM;

    // Load Q tile: 64 rows x 64 d, float4
    #pragma unroll
    for (int it = 0; it < 4; it++) {
        int vid = tid + it * 256;    // 0..1023
        int r  = vid >> 4;           // 0..63
        int c4 = (vid & 15) * 4;     // 0..60
        float4 val = *reinterpret_cast<const float4*>(
            &q[(((size_t)b * TT + q0 + r) * HH + h) * DD + c4]);
        Qs[r * LDP + c4 + 0] = val.x;
        Qs[r * LDP + c4 + 1] = val.y;
        Qs[r * LDP + c4 + 2] = val.z;
        Qs[r * LDP + c4 + 3] = val.w;
    }
    if (tid < ATM) {
        row_m[tid] = -1e30f;
        row_l[tid] = 0.f;
    }

    float accO[16];
    #pragma unroll
    for (int i = 0; i < 16; i++) accO[i] = 0.f;

    const int iy = (tid >> 4) * 4;   // row group (S compute + O update rows)
    const int jx = (tid & 15) * 4;   // col group (S cols / O d-cols)
    const float scale = 1.0f / 8.0f; // 1/sqrt(64)

    __syncthreads();

    const int nkt = qt + 1;          // causal: tiles 0..qt
    for (int kt = 0; kt < nkt; kt++) {
        const int k0 = kt * ATN;
        // Load K and V tiles
        #pragma unroll
        for (int it = 0; it < 4; it++) {
            int vid = tid + it * 256;
            int r  = vid >> 4;
            int c4 = (vid & 15) * 4;
            size_t goff = (((size_t)b * TT + k0 + r) * HH + h) * DD + c4;
            float4 kv4 = *reinterpret_cast<const float4*>(&k[goff]);
            Ks[r * LDP + c4 + 0] = kv4.x;
            Ks[r * LDP + c4 + 1] = kv4.y;
            Ks[r * LDP + c4 + 2] = kv4.z;
            Ks[r * LDP + c4 + 3] = kv4.w;
            float4 vv4 = *reinterpret_cast<const float4*>(&v[goff]);
            Vs[r * LDP + c4 + 0] = vv4.x;
            Vs[r * LDP + c4 + 1] = vv4.y;
            Vs[r * LDP + c4 + 2] = vv4.z;
            Vs[r * LDP + c4 + 3] = vv4.w;
        }
        __syncthreads();

        // S = Q @ K^T  (4x4 microtile per thread)
        float s[4][4];
        #pragma unroll
        for (int i = 0; i < 4; i++)
            #pragma unroll
            for (int j = 0; j < 4; j++) s[i][j] = 0.f;
        #pragma unroll 8
        for (int d = 0; d < DD; d++) {
            float qa[4], kb[4];
            #pragma unroll
            for (int i = 0; i < 4; i++) qa[i] = Qs[(iy + i) * LDP + d];
            #pragma unroll
            for (int j = 0; j < 4; j++) kb[j] = Ks[(jx + j) * LDP + d];
            #pragma unroll
            for (int i = 0; i < 4; i++)
                #pragma unroll
                for (int j = 0; j < 4; j++)
                    s[i][j] = fmaf(qa[i], kb[j], s[i][j]);
        }
        // scale + causal mask + store to smem
        const bool diag = (kt == qt);
        #pragma unroll
        for (int i = 0; i < 4; i++) {
            #pragma unroll
            for (int j = 0; j < 4; j++) {
                float val = s[i][j] * scale;
                if (diag && (k0 + jx + j) > (q0 + iy + i)) val = -1e30f;
                Ss[(iy + i) * LDP + jx + j] = val;
            }
        }
        __syncthreads();

        // Online softmax: 4 threads per row (quad-aligned within warps),
        // all 256 threads active. shfl_xor quad reduction.
        {
            const int row = tid >> 2;
            const int sub = tid & 3;
            float m_old = row_m[row];
            float mx = m_old;
            #pragma unroll 4
            for (int j = sub; j < ATN; j += 4)
                mx = fmaxf(mx, Ss[row * LDP + j]);
            mx = fmaxf(mx, __shfl_xor_sync(0xffffffffu, mx, 1));
            mx = fmaxf(mx, __shfl_xor_sync(0xffffffffu, mx, 2));
            float lsum = 0.f;
            #pragma unroll 4
            for (int j = sub; j < ATN; j += 4) {
                float p = __expf(Ss[row * LDP + j] - mx);
                Ss[row * LDP + j] = p;
                lsum += p;
            }
            lsum += __shfl_xor_sync(0xffffffffu, lsum, 1);
            lsum += __shfl_xor_sync(0xffffffffu, lsum, 2);
            if (sub == 0) {
                float alpha = __expf(m_old - mx);
                row_alpha[row] = alpha;
                row_m[row] = mx;
                row_l[row] = row_l[row] * alpha + lsum;
            }
        }
        __syncthreads();

        // O = O*alpha + P @ V   (4 rows x 4 d-cols per thread)
        #pragma unroll
        for (int i = 0; i < 4; i++) {
            float a = row_alpha[iy + i];
            #pragma unroll
            for (int d = 0; d < 4; d++) accO[i * 4 + d] *= a;
        }
        #pragma unroll 4
        for (int j = 0; j < ATN; j++) {
            float vv[4];
            #pragma unroll
            for (int d = 0; d < 4; d++) vv[d] = Vs[j * LDP + jx + d];
            #pragma unroll
            for (int i = 0; i < 4; i++) {
                float p = Ss[(iy + i) * LDP + j];
                #pragma unroll
                for (int d = 0; d < 4; d++)
                    accO[i * 4 + d] = fmaf(p, vv[d], accO[i * 4 + d]);
            }
        }
        __syncthreads();   // before next iteration overwrites Ks/Vs/Ss
    }

    // Normalize and write out: o[b, q0+row, h, d]
    #pragma unroll
    for (int i = 0; i < 4; i++) {
        float inv_l = 1.0f / row_l[iy + i];
        size_t base = (((size_t)b * TT + q0 + iy + i) * HH + h) * DD + jx;
        #pragma unroll
        for (int d = 0; d < 4; d++)
            o[base + d] = accO[i * 4 + d] * inv_l;
    }
}

// ---------------------------------------------------------------------------
// Launch
// ---------------------------------------------------------------------------
extern "C" void kernel_launch(void* const* d_in, const int* in_sizes, int n_in,
                              void* d_out, int out_size)
{
    const float* x  = (const float*)d_in[0];
    const float* Wq = (const float*)d_in[1];
    const float* bq = (const float*)d_in[2];
    const float* Wk = (const float*)d_in[3];
    const float* bk = (const float*)d_in[4];
    const float* Wv = (const float*)d_in[5];
    const float* bv = (const float*)d_in[6];
    const float* Wo = (const float*)d_in[7];
    const float* bo = (const float*)d_in[8];
    float* out = (float*)d_out;

    float *qp, *kp, *vp, *ap;
    cudaGetSymbolAddress((void**)&qp, g_q);
    cudaGetSymbolAddress((void**)&kp, g_k);
    cudaGetSymbolAddress((void**)&vp, g_v);
    cudaGetSymbolAddress((void**)&ap, g_att);

    const dim3 gemm_grid(CC / GBN, MM / GBM);   // (8, 32)

    gemm_nt_bias_kernel<<<gemm_grid, 256>>>(x, Wq, bq, qp, MM, CC, CC);
    gemm_nt_bias_kernel<<<gemm_grid, 256>>>(x, Wk, bk, kp, MM, CC, CC);
    gemm_nt_bias_kernel<<<gemm_grid, 256>>>(x, Wv, bv, vp, MM, CC, CC);

    const size_t att_smem = (size_t)(4 * ATM * LDP + 3 * ATM) * sizeof(float);
    cudaFuncSetAttribute(attention_kernel,
                         cudaFuncAttributeMaxDynamicSharedMemorySize,
                         (int)att_smem);
    attention_kernel<<<dim3(TT / ATM, HH, BB), 256, att_smem>>>(qp, kp, vp, ap);

    gemm_nt_bias_kernel<<<gemm_grid, 256>>>(ap, Wo, bo, out, MM, CC, CC);
}

// round 4
// speedup vs baseline: 1.5076x; 1.5076x over previous
#include <cuda_runtime.h>
#include <cuda_bf16.h>
#include <math.h>
#include <cstdint>

// Problem constants
#define BB 2
#define TT 2048
#define CC 1024
#define HH 16
#define DD 64
#define MM (BB*TT)   // 4096

// ---------------------------------------------------------------------------
// Scratch (allocation-free: __device__ globals)
// ---------------------------------------------------------------------------
__device__ float g_q[MM*CC];
__device__ float g_k[MM*CC];
__device__ float g_v[MM*CC];
__device__ float g_att[MM*CC];

// ---------------------------------------------------------------------------
// mma.sync helpers (sm_100 base target: HMMA path, no tcgen05)
// ---------------------------------------------------------------------------
__device__ __forceinline__ uint32_t f2tf(float f) {
    uint32_t u;
    asm("cvt.rna.tf32.f32 %0, %1;" : "=r"(u) : "f"(f));
    return u;
}

__device__ __forceinline__ void mma_tf32(float* d, const uint32_t* a, const uint32_t* b) {
    asm volatile(
        "mma.sync.aligned.m16n8k8.row.col.f32.tf32.tf32.f32 "
        "{%0,%1,%2,%3}, {%4,%5,%6,%7}, {%8,%9}, {%0,%1,%2,%3};"
        : "+f"(d[0]), "+f"(d[1]), "+f"(d[2]), "+f"(d[3])
        : "r"(a[0]), "r"(a[1]), "r"(a[2]), "r"(a[3]),
          "r"(b[0]), "r"(b[1]));
}

// ===========================================================================
// tf32 mma.sync GEMM:  C[M,N] = A[M,K] @ W[N,K]^T + bias[N]
// CTA tile 128x128, BK=16, 256 threads = 8 warps (2M x 4N), warp tile 64x32.
// Double-buffered smem, one __syncthreads per K-tile.
// grid = (N/128, M/128)
// ===========================================================================
#define GBK 16
#define BKP 20              // padded row stride (uint32) -> conflict-free quads
#define NKT (CC / GBK)      // 64

__global__ __launch_bounds__(256) void gemm_mma_kernel(
    const float* __restrict__ A, const float* __restrict__ W,
    const float* __restrict__ bias, float* __restrict__ C)
{
    __shared__ uint32_t As[2][128 * BKP];
    __shared__ uint32_t Ws[2][128 * BKP];

    const int tid = threadIdx.x;
    const int wid = tid >> 5;
    const int lane = tid & 31;
    const int g  = lane >> 2;      // groupID
    const int tg = lane & 3;       // threadID_in_group
    const int warp_m = wid >> 2;   // 0..1
    const int warp_n = wid & 3;    // 0..3
    const int m0 = blockIdx.y * 128;
    const int n0 = blockIdx.x * 128;
    const float* Ag = A + (size_t)m0 * CC;
    const float* Wg = W + (size_t)n0 * CC;

    float d[4][4][4];
    #pragma unroll
    for (int mt = 0; mt < 4; mt++)
        #pragma unroll
        for (int nt = 0; nt < 4; nt++)
            #pragma unroll
            for (int r = 0; r < 4; r++) d[mt][nt][r] = 0.f;

    // Tile-load mapping: thread handles rows r0 and r0+64, 4 consecutive floats at c0
    const int r0 = tid >> 2;
    const int c0 = (tid & 3) * 4;

    float4 a4[2], w4[2];

    // Preload tile 0
    #pragma unroll
    for (int i = 0; i < 2; i++) {
        a4[i] = *reinterpret_cast<const float4*>(Ag + (size_t)(r0 + i * 64) * CC + c0);
        w4[i] = *reinterpret_cast<const float4*>(Wg + (size_t)(r0 + i * 64) * CC + c0);
    }
    #pragma unroll
    for (int i = 0; i < 2; i++) {
        int r = r0 + i * 64;
        uint32_t* pa = &As[0][r * BKP + c0];
        pa[0] = f2tf(a4[i].x); pa[1] = f2tf(a4[i].y);
        pa[2] = f2tf(a4[i].z); pa[3] = f2tf(a4[i].w);
        uint32_t* pw = &Ws[0][r * BKP + c0];
        pw[0] = f2tf(w4[i].x); pw[1] = f2tf(w4[i].y);
        pw[2] = f2tf(w4[i].z); pw[3] = f2tf(w4[i].w);
    }
    __syncthreads();

    for (int kt = 0; kt < NKT; kt++) {
        const int buf = kt & 1;
        if (kt < NKT - 1) {
            const int koff = (kt + 1) * GBK;
            #pragma unroll
            for (int i = 0; i < 2; i++) {
                a4[i] = *reinterpret_cast<const float4*>(
                    Ag + (size_t)(r0 + i * 64) * CC + koff + c0);
                w4[i] = *reinterpret_cast<const float4*>(
                    Wg + (size_t)(r0 + i * 64) * CC + koff + c0);
            }
        }

        // Compute on current buffer: 2 k-steps of k=8
        #pragma unroll
        for (int ks = 0; ks < 2; ks++) {
            const int k0 = ks * 8;
            uint32_t af[4][4], bf[4][2];
            #pragma unroll
            for (int mt = 0; mt < 4; mt++) {
                const int row = warp_m * 64 + mt * 16 + g;
                const uint32_t* p  = &As[buf][row * BKP + k0 + tg];
                const uint32_t* p8 = p + 8 * BKP;
                af[mt][0] = p[0];
                af[mt][1] = p8[0];
                af[mt][2] = p[4];
                af[mt][3] = p8[4];
            }
            #pragma unroll
            for (int nt = 0; nt < 4; nt++) {
                const int rn = warp_n * 32 + nt * 8 + g;
                const uint32_t* p = &Ws[buf][rn * BKP + k0 + tg];
                bf[nt][0] = p[0];
                bf[nt][1] = p[4];
            }
            #pragma unroll
            for (int mt = 0; mt < 4; mt++)
                #pragma unroll
                for (int nt = 0; nt < 4; nt++)
                    mma_tf32(d[mt][nt], af[mt], bf[nt]);
        }

        // Stage next tile into the other buffer (disjoint from current reads)
        if (kt < NKT - 1) {
            #pragma unroll
            for (int i = 0; i < 2; i++) {
                int r = r0 + i * 64;
                uint32_t* pa = &As[buf ^ 1][r * BKP + c0];
                pa[0] = f2tf(a4[i].x); pa[1] = f2tf(a4[i].y);
                pa[2] = f2tf(a4[i].z); pa[3] = f2tf(a4[i].w);
                uint32_t* pw = &Ws[buf ^ 1][r * BKP + c0];
                pw[0] = f2tf(w4[i].x); pw[1] = f2tf(w4[i].y);
                pw[2] = f2tf(w4[i].z); pw[3] = f2tf(w4[i].w);
            }
        }
        __syncthreads();
    }

    // Epilogue: C-fragment layout c0:(g, tg*2) c1:(g, tg*2+1) c2:(g+8,..) c3
    #pragma unroll
    for (int mt = 0; mt < 4; mt++) {
        const int row = m0 + warp_m * 64 + mt * 16 + g;
        #pragma unroll
        for (int nt = 0; nt < 4; nt++) {
            const int col = n0 + warp_n * 32 + nt * 8 + tg * 2;
            float2 bv = *reinterpret_cast<const float2*>(bias + col);
            float2 o0 = make_float2(d[mt][nt][0] + bv.x, d[mt][nt][1] + bv.y);
            float2 o1 = make_float2(d[mt][nt][2] + bv.x, d[mt][nt][3] + bv.y);
            *reinterpret_cast<float2*>(C + (size_t)row * CC + col) = o0;
            *reinterpret_cast<float2*>(C + (size_t)(row + 8) * CC + col) = o1;
        }
    }
}

// ---------------------------------------------------------------------------
// Flash attention (causal), fp32.  (unchanged from the passing R2 kernel)
// grid = (T/64, H, B), 256 threads.
// ---------------------------------------------------------------------------
#define ATM 64
#define ATN 64
#define LDP 65

__global__ __launch_bounds__(256) void attention_kernel(
    const float* __restrict__ q, const float* __restrict__ k,
    const float* __restrict__ v, float* __restrict__ o)
{
    extern __shared__ __align__(16) float sm[];
    float* Qs = sm;
    float* Ks = Qs + ATM * LDP;
    float* Vs = Ks + ATN * LDP;
    float* Ss = Vs + ATN * LDP;
    float* row_m     = Ss + ATM * LDP;
    float* row_l     = row_m + ATM;
    float* row_alpha = row_l + ATM;

    const int tid = threadIdx.x;
    const int qt = blockIdx.x;
    const int h  = blockIdx.y;
    const int b  = blockIdx.z;
    const int q0 = qt * ATM;

    #pragma unroll
    for (int it = 0; it < 4; it++) {
        int vid = tid + it * 256;
        int r  = vid >> 4;
        int c4 = (vid & 15) * 4;
        float4 val = *reinterpret_cast<const float4*>(
            &q[(((size_t)b * TT + q0 + r) * HH + h) * DD + c4]);
        Qs[r * LDP + c4 + 0] = val.x;
        Qs[r * LDP + c4 + 1] = val.y;
        Qs[r * LDP + c4 + 2] = val.z;
        Qs[r * LDP + c4 + 3] = val.w;
    }
    if (tid < ATM) {
        row_m[tid] = -1e30f;
        row_l[tid] = 0.f;
    }

    float accO[16];
    #pragma unroll
    for (int i = 0; i < 16; i++) accO[i] = 0.f;

    const int iy = (tid >> 4) * 4;
    const int jx = (tid & 15) * 4;
    const float scale = 1.0f / 8.0f;

    __syncthreads();

    const int nkt = qt + 1;
    for (int kt = 0; kt < nkt; kt++) {
        const int k0 = kt * ATN;
        #pragma unroll
        for (int it = 0; it < 4; it++) {
            int vid = tid + it * 256;
            int r  = vid >> 4;
            int c4 = (vid & 15) * 4;
            size_t goff = (((size_t)b * TT + k0 + r) * HH + h) * DD + c4;
            float4 kv4 = *reinterpret_cast<const float4*>(&k[goff]);
            Ks[r * LDP + c4 + 0] = kv4.x;
            Ks[r * LDP + c4 + 1] = kv4.y;
            Ks[r * LDP + c4 + 2] = kv4.z;
            Ks[r * LDP + c4 + 3] = kv4.w;
            float4 vv4 = *reinterpret_cast<const float4*>(&v[goff]);
            Vs[r * LDP + c4 + 0] = vv4.x;
            Vs[r * LDP + c4 + 1] = vv4.y;
            Vs[r * LDP + c4 + 2] = vv4.z;
            Vs[r * LDP + c4 + 3] = vv4.w;
        }
        __syncthreads();

        float s[4][4];
        #pragma unroll
        for (int i = 0; i < 4; i++)
            #pragma unroll
            for (int j = 0; j < 4; j++) s[i][j] = 0.f;
        #pragma unroll 8
        for (int dd = 0; dd < DD; dd++) {
            float qa[4], kb[4];
            #pragma unroll
            for (int i = 0; i < 4; i++) qa[i] = Qs[(iy + i) * LDP + dd];
            #pragma unroll
            for (int j = 0; j < 4; j++) kb[j] = Ks[(jx + j) * LDP + dd];
            #pragma unroll
            for (int i = 0; i < 4; i++)
                #pragma unroll
                for (int j = 0; j < 4; j++)
                    s[i][j] = fmaf(qa[i], kb[j], s[i][j]);
        }
        const bool diag = (kt == qt);
        #pragma unroll
        for (int i = 0; i < 4; i++) {
            #pragma unroll
            for (int j = 0; j < 4; j++) {
                float val = s[i][j] * scale;
                if (diag && (k0 + jx + j) > (q0 + iy + i)) val = -1e30f;
                Ss[(iy + i) * LDP + jx + j] = val;
            }
        }
        __syncthreads();

        {
            const int row = tid >> 2;
            const int sub = tid & 3;
            float m_old = row_m[row];
            float mx = m_old;
            #pragma unroll 4
            for (int j = sub; j < ATN; j += 4)
                mx = fmaxf(mx, Ss[row * LDP + j]);
            mx = fmaxf(mx, __shfl_xor_sync(0xffffffffu, mx, 1));
            mx = fmaxf(mx, __shfl_xor_sync(0xffffffffu, mx, 2));
            float lsum = 0.f;
            #pragma unroll 4
            for (int j = sub; j < ATN; j += 4) {
                float p = __expf(Ss[row * LDP + j] - mx);
                Ss[row * LDP + j] = p;
                lsum += p;
            }
            lsum += __shfl_xor_sync(0xffffffffu, lsum, 1);
            lsum += __shfl_xor_sync(0xffffffffu, lsum, 2);
            if (sub == 0) {
                float alpha = __expf(m_old - mx);
                row_alpha[row] = alpha;
                row_m[row] = mx;
                row_l[row] = row_l[row] * alpha + lsum;
            }
        }
        __syncthreads();

        #pragma unroll
        for (int i = 0; i < 4; i++) {
            float a = row_alpha[iy + i];
            #pragma unroll
            for (int dd = 0; dd < 4; dd++) accO[i * 4 + dd] *= a;
        }
        #pragma unroll 4
        for (int j = 0; j < ATN; j++) {
            float vv[4];
            #pragma unroll
            for (int dd = 0; dd < 4; dd++) vv[dd] = Vs[j * LDP + jx + dd];
            #pragma unroll
            for (int i = 0; i < 4; i++) {
                float p = Ss[(iy + i) * LDP + j];
                #pragma unroll
                for (int dd = 0; dd < 4; dd++)
                    accO[i * 4 + dd] = fmaf(p, vv[dd], accO[i * 4 + dd]);
            }
        }
        __syncthreads();
    }

    #pragma unroll
    for (int i = 0; i < 4; i++) {
        float inv_l = 1.0f / row_l[iy + i];
        size_t base = (((size_t)b * TT + q0 + iy + i) * HH + h) * DD + jx;
        #pragma unroll
        for (int dd = 0; dd < 4; dd++)
            o[base + dd] = accO[i * 4 + dd] * inv_l;
    }
}

// ---------------------------------------------------------------------------
// Launch
// ---------------------------------------------------------------------------
extern "C" void kernel_launch(void* const* d_in, const int* in_sizes, int n_in,
                              void* d_out, int out_size)
{
    const float* x  = (const float*)d_in[0];
    const float* Wq = (const float*)d_in[1];
    const float* bq = (const float*)d_in[2];
    const float* Wk = (const float*)d_in[3];
    const float* bk = (const float*)d_in[4];
    const float* Wv = (const float*)d_in[5];
    const float* bv = (const float*)d_in[6];
    const float* Wo = (const float*)d_in[7];
    const float* bo = (const float*)d_in[8];
    float* out = (float*)d_out;

    float *qp, *kp, *vp, *ap;
    cudaGetSymbolAddress((void**)&qp, g_q);
    cudaGetSymbolAddress((void**)&kp, g_k);
    cudaGetSymbolAddress((void**)&vp, g_v);
    cudaGetSymbolAddress((void**)&ap, g_att);

    const dim3 gemm_grid(CC / 128, MM / 128);   // (8, 32)

    gemm_mma_kernel<<<gemm_grid, 256>>>(x, Wq, bq, qp);
    gemm_mma_kernel<<<gemm_grid, 256>>>(x, Wk, bk, kp);
    gemm_mma_kernel<<<gemm_grid, 256>>>(x, Wv, bv, vp);

    const size_t att_smem = (size_t)(4 * ATM * LDP + 3 * ATM) * sizeof(float);
    cudaFuncSetAttribute(attention_kernel,
                         cudaFuncAttributeMaxDynamicSharedMemorySize,
                         (int)att_smem);
    attention_kernel<<<dim3(TT / ATM, HH, BB), 256, att_smem>>>(qp, kp, vp, ap);

    gemm_mma_kernel<<<gemm_grid, 256>>>(ap, Wo, bo, out);
}

// round 6
// speedup vs baseline: 3.0967x; 2.0540x over previous
#include <cuda_runtime.h>
#include <cuda_bf16.h>
#include <math.h>
#include <cstdint>

// Problem constants
#define BB 2
#define TT 2048
#define CC 1024
#define HH 16
#define DD 64
#define MM (BB*TT)   // 4096

// ---------------------------------------------------------------------------
// Scratch (allocation-free: __device__ globals)
// ---------------------------------------------------------------------------
__device__ float g_q[MM*CC];
__device__ float g_k[MM*CC];
__device__ float g_v[MM*CC];
__device__ float g_att[MM*CC];

// ---------------------------------------------------------------------------
// mma.sync helpers (sm_100 base target: HMMA path, no tcgen05)
// ---------------------------------------------------------------------------
__device__ __forceinline__ uint32_t f2tf(float f) {
    uint32_t u;
    asm("cvt.rna.tf32.f32 %0, %1;" : "=r"(u) : "f"(f));
    return u;
}

__device__ __forceinline__ void mma_tf32(float* d, const uint32_t* a, const uint32_t* b) {
    asm volatile(
        "mma.sync.aligned.m16n8k8.row.col.f32.tf32.tf32.f32 "
        "{%0,%1,%2,%3}, {%4,%5,%6,%7}, {%8,%9}, {%0,%1,%2,%3};"
        : "+f"(d[0]), "+f"(d[1]), "+f"(d[2]), "+f"(d[3])
        : "r"(a[0]), "r"(a[1]), "r"(a[2]), "r"(a[3]),
          "r"(b[0]), "r"(b[1]));
}

__device__ __forceinline__ uint32_t smem_u32(const void* p) {
    uint32_t a;
    asm("{ .reg .u64 t; cvta.to.shared.u64 t, %1; cvt.u32.u64 %0, t; }"
        : "=r"(a) : "l"(p));
    return a;
}

__device__ __forceinline__ void cp_async16(uint32_t dst, const void* src) {
    asm volatile("cp.async.ca.shared.global [%0], [%1], 16;" :: "r"(dst), "l"(src));
}

// ===========================================================================
// tf32 mma.sync GEMM:  C[M,N] = A[M,K] @ W[N,K]^T + bias[N]   (unchanged R4)
// CTA tile 128x128, BK=16, 256 threads = 8 warps (2M x 4N), warp tile 64x32.
// ===========================================================================
#define GBK 16
#define BKP 20
#define NKT (CC / GBK)      // 64

__global__ __launch_bounds__(256) void gemm_mma_kernel(
    const float* __restrict__ A, const float* __restrict__ W,
    const float* __restrict__ bias, float* __restrict__ C)
{
    __shared__ uint32_t As[2][128 * BKP];
    __shared__ uint32_t Ws[2][128 * BKP];

    const int tid = threadIdx.x;
    const int wid = tid >> 5;
    const int lane = tid & 31;
    const int g  = lane >> 2;
    const int tg = lane & 3;
    const int warp_m = wid >> 2;
    const int warp_n = wid & 3;
    const int m0 = blockIdx.y * 128;
    const int n0 = blockIdx.x * 128;
    const float* Ag = A + (size_t)m0 * CC;
    const float* Wg = W + (size_t)n0 * CC;

    float d[4][4][4];
    #pragma unroll
    for (int mt = 0; mt < 4; mt++)
        #pragma unroll
        for (int nt = 0; nt < 4; nt++)
            #pragma unroll
            for (int r = 0; r < 4; r++) d[mt][nt][r] = 0.f;

    const int r0 = tid >> 2;
    const int c0 = (tid & 3) * 4;

    float4 a4[2], w4[2];

    #pragma unroll
    for (int i = 0; i < 2; i++) {
        a4[i] = *reinterpret_cast<const float4*>(Ag + (size_t)(r0 + i * 64) * CC + c0);
        w4[i] = *reinterpret_cast<const float4*>(Wg + (size_t)(r0 + i * 64) * CC + c0);
    }
    #pragma unroll
    for (int i = 0; i < 2; i++) {
        int r = r0 + i * 64;
        uint32_t* pa = &As[0][r * BKP + c0];
        pa[0] = f2tf(a4[i].x); pa[1] = f2tf(a4[i].y);
        pa[2] = f2tf(a4[i].z); pa[3] = f2tf(a4[i].w);
        uint32_t* pw = &Ws[0][r * BKP + c0];
        pw[0] = f2tf(w4[i].x); pw[1] = f2tf(w4[i].y);
        pw[2] = f2tf(w4[i].z); pw[3] = f2tf(w4[i].w);
    }
    __syncthreads();

    for (int kt = 0; kt < NKT; kt++) {
        const int buf = kt & 1;
        if (kt < NKT - 1) {
            const int koff = (kt + 1) * GBK;
            #pragma unroll
            for (int i = 0; i < 2; i++) {
                a4[i] = *reinterpret_cast<const float4*>(
                    Ag + (size_t)(r0 + i * 64) * CC + koff + c0);
                w4[i] = *reinterpret_cast<const float4*>(
                    Wg + (size_t)(r0 + i * 64) * CC + koff + c0);
            }
        }

        #pragma unroll
        for (int ks = 0; ks < 2; ks++) {
            const int k0 = ks * 8;
            uint32_t af[4][4], bf[4][2];
            #pragma unroll
            for (int mt = 0; mt < 4; mt++) {
                const int row = warp_m * 64 + mt * 16 + g;
                const uint32_t* p  = &As[buf][row * BKP + k0 + tg];
                const uint32_t* p8 = p + 8 * BKP;
                af[mt][0] = p[0];
                af[mt][1] = p8[0];
                af[mt][2] = p[4];
                af[mt][3] = p8[4];
            }
            #pragma unroll
            for (int nt = 0; nt < 4; nt++) {
                const int rn = warp_n * 32 + nt * 8 + g;
                const uint32_t* p = &Ws[buf][rn * BKP + k0 + tg];
                bf[nt][0] = p[0];
                bf[nt][1] = p[4];
            }
            #pragma unroll
            for (int mt = 0; mt < 4; mt++)
                #pragma unroll
                for (int nt = 0; nt < 4; nt++)
                    mma_tf32(d[mt][nt], af[mt], bf[nt]);
        }

        if (kt < NKT - 1) {
            #pragma unroll
            for (int i = 0; i < 2; i++) {
                int r = r0 + i * 64;
                uint32_t* pa = &As[buf ^ 1][r * BKP + c0];
                pa[0] = f2tf(a4[i].x); pa[1] = f2tf(a4[i].y);
                pa[2] = f2tf(a4[i].z); pa[3] = f2tf(a4[i].w);
                uint32_t* pw = &Ws[buf ^ 1][r * BKP + c0];
                pw[0] = f2tf(w4[i].x); pw[1] = f2tf(w4[i].y);
                pw[2] = f2tf(w4[i].z); pw[3] = f2tf(w4[i].w);
            }
        }
        __syncthreads();
    }

    #pragma unroll
    for (int mt = 0; mt < 4; mt++) {
        const int row = m0 + warp_m * 64 + mt * 16 + g;
        #pragma unroll
        for (int nt = 0; nt < 4; nt++) {
            const int col = n0 + warp_n * 32 + nt * 8 + tg * 2;
            float2 bv = *reinterpret_cast<const float2*>(bias + col);
            float2 o0 = make_float2(d[mt][nt][0] + bv.x, d[mt][nt][1] + bv.y);
            float2 o1 = make_float2(d[mt][nt][2] + bv.x, d[mt][nt][3] + bv.y);
            *reinterpret_cast<float2*>(C + (size_t)row * CC + col) = o0;
            *reinterpret_cast<float2*>(C + (size_t)(row + 8) * CC + col) = o1;
        }
    }
}

// ===========================================================================
// Tensor-core flash attention (causal), tf32 mma.sync.
// CTA: 128 q rows, 8 warps (16 q rows/warp), kv tile 64, D=64.
// grid = (T/128, H, B) = (16, 16, 2), 256 threads.
// Scale 1/sqrt(D) folded into Q. P->A fragment fixup via register shuffles.
// K/V double-buffered via cp.async. fp32 bits fed as tf32 (truncation).
// ===========================================================================
#define AQ 128
#define AKV 64
#define KP 68               // K/Q smem row pad (floats): bank = 4g+tg (bijective)
#define VP 72               // V   smem row pad (floats): bank = 8tg+g (bijective)
#define SM_K0 0
#define SM_K1 (64*KP)
#define SM_V0 (2*64*KP)
#define SM_V1 (2*64*KP + 64*VP)
#define ATT_SMEM_BYTES ((2*64*KP + 2*64*VP) * 4)   // 71680

__global__ __launch_bounds__(256, 2) void attention_mma_kernel(
    const float* __restrict__ Qg, const float* __restrict__ Kg,
    const float* __restrict__ Vg, float* __restrict__ Og)
{
    extern __shared__ __align__(16) float smf[];
    const uint32_t sbase = smem_u32(smf);
    const int tid = threadIdx.x;
    const int w = tid >> 5;
    const int lane = tid & 31;
    const int g = lane >> 2, tg = lane & 3;
    const int qt = blockIdx.x, h = blockIdx.y, b = blockIdx.z;
    const int q0 = qt * AQ;
    const size_t bh = (size_t)b * TT * CC + (size_t)h * DD;  // + t*CC + d

    // --- stage Q (scaled by 1/sqrt(D)) into smem [128][KP] ---
    {
        const float sc = 0.125f;
        #pragma unroll
        for (int j = 0; j < 8; j++) {
            int idx = tid + j * 256;           // 0..2047
            int r = idx >> 4, cc = (idx & 15) * 4;
            float4 val = *reinterpret_cast<const float4*>(
                Qg + bh + (size_t)(q0 + r) * CC + cc);
            float* dst = smf + r * KP + cc;
            dst[0] = val.x * sc; dst[1] = val.y * sc;
            dst[2] = val.z * sc; dst[3] = val.w * sc;
        }
    }
    __syncthreads();

    // --- Q A-fragments to registers (persist whole kernel) ---
    uint32_t qa[8][4];
    {
        const uint32_t* Qs = reinterpret_cast<const uint32_t*>(smf);
        const int r0 = (w * 16 + g) * KP;
        #pragma unroll
        for (int kk = 0; kk < 8; kk++) {
            qa[kk][0] = Qs[r0 + kk * 8 + tg];
            qa[kk][1] = Qs[r0 + 8 * KP + kk * 8 + tg];
            qa[kk][2] = Qs[r0 + kk * 8 + tg + 4];
            qa[kk][3] = Qs[r0 + 8 * KP + kk * 8 + tg + 4];
        }
    }
    __syncthreads();   // Q stage area becomes K buffers

    float s[8][4], oo[8][4];
    float m0 = -1e30f, m1 = -1e30f, l0 = 0.f, l1 = 0.f;
    #pragma unroll
    for (int nt = 0; nt < 8; nt++) {
        oo[nt][0] = oo[nt][1] = oo[nt][2] = oo[nt][3] = 0.f;
    }

    const int ntiles = 2 * qt + 2;
    const int wrow_first = q0 + w * 16;
    const int wrow_last  = wrow_first + 15;

    const uint32_t kbuf_b[2] = { sbase + SM_K0 * 4u, sbase + SM_K1 * 4u };
    const uint32_t vbuf_b[2] = { sbase + SM_V0 * 4u, sbase + SM_V1 * 4u };

    // preload tile 0
    #pragma unroll
    for (int j = 0; j < 4; j++) {
        int idx = tid + j * 256;               // 0..1023
        int r = idx >> 4, cc = (idx & 15) * 4;
        const float* srcK = Kg + bh + (size_t)r * CC + cc;
        const float* srcV = Vg + bh + (size_t)r * CC + cc;
        cp_async16(kbuf_b[0] + (uint32_t)(r * KP + cc) * 4u, srcK);
        cp_async16(vbuf_b[0] + (uint32_t)(r * VP + cc) * 4u, srcV);
    }
    asm volatile("cp.async.commit_group;");
    asm volatile("cp.async.wait_group 0;");
    __syncthreads();

    for (int t = 0; t < ntiles; t++) {
        const int buf = t & 1;
        if (t + 1 < ntiles) {
            const int kv0n = (t + 1) * AKV;
            #pragma unroll
            for (int j = 0; j < 4; j++) {
                int idx = tid + j * 256;
                int r = idx >> 4, cc = (idx & 15) * 4;
                const float* srcK = Kg + bh + (size_t)(kv0n + r) * CC + cc;
                const float* srcV = Vg + bh + (size_t)(kv0n + r) * CC + cc;
                cp_async16(kbuf_b[buf ^ 1] + (uint32_t)(r * KP + cc) * 4u, srcK);
                cp_async16(vbuf_b[buf ^ 1] + (uint32_t)(r * VP + cc) * 4u, srcV);
            }
            asm volatile("cp.async.commit_group;");
        }

        const int kv0 = t * AKV;
        if (kv0 <= wrow_last) {   // warp has at least one unmasked element
            const uint32_t* Ks = reinterpret_cast<const uint32_t*>(smf)
                                 + (buf ? SM_K1 : SM_K0);
            const uint32_t* Vs = reinterpret_cast<const uint32_t*>(smf)
                                 + (buf ? SM_V1 : SM_V0);
            // ---- S = Q K^T ----
            #pragma unroll
            for (int nt = 0; nt < 8; nt++) {
                s[nt][0] = s[nt][1] = s[nt][2] = s[nt][3] = 0.f;
            }
            #pragma unroll
            for (int nt = 0; nt < 8; nt++) {
                const int rb = (nt * 8 + g) * KP;
                #pragma unroll
                for (int kk = 0; kk < 8; kk++) {
                    uint32_t bb[2] = { Ks[rb + kk * 8 + tg], Ks[rb + kk * 8 + tg + 4] };
                    mma_tf32(s[nt], qa[kk], bb);
                }
            }
            // ---- causal mask (diagonal tiles only) ----
            if (kv0 + AKV - 1 > wrow_first) {
                const int r0a = wrow_first + g, r1a = r0a + 8;
                #pragma unroll
                for (int nt = 0; nt < 8; nt++) {
                    const int c = kv0 + nt * 8 + 2 * tg;
                    if (c     > r0a) s[nt][0] = -1e30f;
                    if (c + 1 > r0a) s[nt][1] = -1e30f;
                    if (c     > r1a) s[nt][2] = -1e30f;
                    if (c + 1 > r1a) s[nt][3] = -1e30f;
                }
            }
            // ---- online softmax (register-resident) ----
            float mx0 = m0, mx1 = m1;
            #pragma unroll
            for (int nt = 0; nt < 8; nt++) {
                mx0 = fmaxf(mx0, fmaxf(s[nt][0], s[nt][1]));
                mx1 = fmaxf(mx1, fmaxf(s[nt][2], s[nt][3]));
            }
            mx0 = fmaxf(mx0, __shfl_xor_sync(0xffffffffu, mx0, 1));
            mx0 = fmaxf(mx0, __shfl_xor_sync(0xffffffffu, mx0, 2));
            mx1 = fmaxf(mx1, __shfl_xor_sync(0xffffffffu, mx1, 1));
            mx1 = fmaxf(mx1, __shfl_xor_sync(0xffffffffu, mx1, 2));
            const float al0 = __expf(m0 - mx0), al1 = __expf(m1 - mx1);
            m0 = mx0; m1 = mx1;
            float sum0 = 0.f, sum1 = 0.f;
            #pragma unroll
            for (int nt = 0; nt < 8; nt++) {
                s[nt][0] = __expf(s[nt][0] - mx0); sum0 += s[nt][0];
                s[nt][1] = __expf(s[nt][1] - mx0); sum0 += s[nt][1];
                s[nt][2] = __expf(s[nt][2] - mx1); sum1 += s[nt][2];
                s[nt][3] = __expf(s[nt][3] - mx1); sum1 += s[nt][3];
            }
            l0 = l0 * al0 + sum0;
            l1 = l1 * al1 + sum1;
            #pragma unroll
            for (int nt = 0; nt < 8; nt++) {
                oo[nt][0] *= al0; oo[nt][1] *= al0;
                oo[nt][2] *= al1; oo[nt][3] *= al1;
            }
            // ---- P (C-frag) -> A-frag via shuffles, in place ----
            const int base = lane & ~3;
            #pragma unroll
            for (int kk = 0; kk < 8; kk++) {
                const int srcA = base | (tg >> 1);
                const int srcB = srcA + 2;
                float x0 = __shfl_sync(0xffffffffu, s[kk][0], srcA);
                float x1 = __shfl_sync(0xffffffffu, s[kk][1], srcA);
                float x2 = __shfl_sync(0xffffffffu, s[kk][2], srcA);
                float x3 = __shfl_sync(0xffffffffu, s[kk][3], srcA);
                float y0 = __shfl_sync(0xffffffffu, s[kk][0], srcB);
                float y1 = __shfl_sync(0xffffffffu, s[kk][1], srcB);
                float y2 = __shfl_sync(0xffffffffu, s[kk][2], srcB);
                float y3 = __shfl_sync(0xffffffffu, s[kk][3], srcB);
                const bool odd = tg & 1;
                s[kk][0] = odd ? x1 : x0;   // a0: row g,   col tg
                s[kk][1] = odd ? x3 : x2;   // a1: row g+8, col tg
                s[kk][2] = odd ? y1 : y0;   // a2: row g,   col tg+4
                s[kk][3] = odd ? y3 : y2;   // a3: row g+8, col tg+4
            }
            // ---- O += P V ----
            #pragma unroll
            for (int nt = 0; nt < 8; nt++) {
                #pragma unroll
                for (int kk = 0; kk < 8; kk++) {
                    uint32_t bb[2] = { Vs[(kk * 8 + tg) * VP + nt * 8 + g],
                                       Vs[(kk * 8 + tg + 4) * VP + nt * 8 + g] };
                    mma_tf32(oo[nt], reinterpret_cast<uint32_t*>(s[kk]), bb);
                }
            }
        }
        if (t + 1 < ntiles) asm volatile("cp.async.wait_group 0;");
        __syncthreads();
    }

    // ---- finalize: reduce l over the quad, normalize, store ----
    l0 += __shfl_xor_sync(0xffffffffu, l0, 1);
    l0 += __shfl_xor_sync(0xffffffffu, l0, 2);
    l1 += __shfl_xor_sync(0xffffffffu, l1, 1);
    l1 += __shfl_xor_sync(0xffffffffu, l1, 2);
    const float inv0 = 1.f / l0, inv1 = 1.f / l1;
    const int r0a = q0 + w * 16 + g, r1a = r0a + 8;
    #pragma unroll
    for (int nt = 0; nt < 8; nt++) {
        const int c = nt * 8 + 2 * tg;
        *reinterpret_cast<float2*>(Og + bh + (size_t)r0a * CC + c) =
            make_float2(oo[nt][0] * inv0, oo[nt][1] * inv0);
        *reinterpret_cast<float2*>(Og + bh + (size_t)r1a * CC + c) =
            make_float2(oo[nt][2] * inv1, oo[nt][3] * inv1);
    }
}

// ---------------------------------------------------------------------------
// Launch
// ---------------------------------------------------------------------------
extern "C" void kernel_launch(void* const* d_in, const int* in_sizes, int n_in,
                              void* d_out, int out_size)
{
    const float* x  = (const float*)d_in[0];
    const float* Wq = (const float*)d_in[1];
    const float* bq = (const float*)d_in[2];
    const float* Wk = (const float*)d_in[3];
    const float* bk = (const float*)d_in[4];
    const float* Wv = (const float*)d_in[5];
    const float* bv = (const float*)d_in[6];
    const float* Wo = (const float*)d_in[7];
    const float* bo = (const float*)d_in[8];
    float* out = (float*)d_out;

    float *qp, *kp, *vp, *ap;
    cudaGetSymbolAddress((void**)&qp, g_q);
    cudaGetSymbolAddress((void**)&kp, g_k);
    cudaGetSymbolAddress((void**)&vp, g_v);
    cudaGetSymbolAddress((void**)&ap, g_att);

    const dim3 gemm_grid(CC / 128, MM / 128);   // (8, 32)

    gemm_mma_kernel<<<gemm_grid, 256>>>(x, Wq, bq, qp);
    gemm_mma_kernel<<<gemm_grid, 256>>>(x, Wk, bk, kp);
    gemm_mma_kernel<<<gemm_grid, 256>>>(x, Wv, bv, vp);

    cudaFuncSetAttribute(attention_mma_kernel,
                         cudaFuncAttributeMaxDynamicSharedMemorySize,
                         ATT_SMEM_BYTES);
    attention_mma_kernel<<<dim3(TT / AQ, HH, BB), 256, ATT_SMEM_BYTES>>>(
        qp, kp, vp, ap);

    gemm_mma_kernel<<<gemm_grid, 256>>>(ap, Wo, bo, out);
}

// round 7
// speedup vs baseline: 3.1101x; 1.0043x over previous
#include <cuda_runtime.h>
#include <cuda_bf16.h>
#include <math.h>
#include <cstdint>

// Problem constants
#define BB 2
#define TT 2048
#define CC 1024
#define HH 16
#define DD 64
#define MM (BB*TT)   // 4096

// ---------------------------------------------------------------------------
// Scratch (allocation-free: __device__ globals)
// ---------------------------------------------------------------------------
__device__ float g_q[MM*CC];
__device__ float g_k[MM*CC];
__device__ float g_v[MM*CC];
__device__ float g_att[MM*CC];

// ---------------------------------------------------------------------------
// mma.sync helpers (sm_100 base target: HMMA path, no tcgen05)
// ---------------------------------------------------------------------------
__device__ __forceinline__ uint32_t f2tf(float f) {
    uint32_t u;
    asm("cvt.rna.tf32.f32 %0, %1;" : "=r"(u) : "f"(f));
    return u;
}

__device__ __forceinline__ void mma_tf32(float* d, const uint32_t* a, const uint32_t* b) {
    asm volatile(
        "mma.sync.aligned.m16n8k8.row.col.f32.tf32.tf32.f32 "
        "{%0,%1,%2,%3}, {%4,%5,%6,%7}, {%8,%9}, {%0,%1,%2,%3};"
        : "+f"(d[0]), "+f"(d[1]), "+f"(d[2]), "+f"(d[3])
        : "r"(a[0]), "r"(a[1]), "r"(a[2]), "r"(a[3]),
          "r"(b[0]), "r"(b[1]));
}

__device__ __forceinline__ uint32_t smem_u32(const void* p) {
    uint32_t a;
    asm("{ .reg .u64 t; cvta.to.shared.u64 t, %1; cvt.u32.u64 %0, t; }"
        : "=r"(a) : "l"(p));
    return a;
}

__device__ __forceinline__ void cp_async16(uint32_t dst, const void* src) {
    asm volatile("cp.async.ca.shared.global [%0], [%1], 16;" :: "r"(dst), "l"(src));
}

// ===========================================================================
// tf32 mma.sync GEMM core:  C[M,N] = A[M,K] @ W[N,K]^T + bias[N]
// CTA tile 128x128, BK=16, 256 threads = 8 warps (2M x 4N), warp tile 64x32.
// ===========================================================================
#define GBK 16
#define BKP 20
#define NKT (CC / GBK)      // 64

__device__ __forceinline__ void gemm_mma_body(
    const float* __restrict__ A, const float* __restrict__ W,
    const float* __restrict__ bias, float* __restrict__ C,
    int m0, int n0,
    uint32_t (*As)[128 * BKP], uint32_t (*Ws)[128 * BKP])
{
    const int tid = threadIdx.x;
    const int wid = tid >> 5;
    const int lane = tid & 31;
    const int g  = lane >> 2;
    const int tg = lane & 3;
    const int warp_m = wid >> 2;
    const int warp_n = wid & 3;
    const float* Ag = A + (size_t)m0 * CC;
    const float* Wg = W + (size_t)n0 * CC;

    float d[4][4][4];
    #pragma unroll
    for (int mt = 0; mt < 4; mt++)
        #pragma unroll
        for (int nt = 0; nt < 4; nt++)
            #pragma unroll
            for (int r = 0; r < 4; r++) d[mt][nt][r] = 0.f;

    const int r0 = tid >> 2;
    const int c0 = (tid & 3) * 4;

    float4 a4[2], w4[2];

    #pragma unroll
    for (int i = 0; i < 2; i++) {
        a4[i] = *reinterpret_cast<const float4*>(Ag + (size_t)(r0 + i * 64) * CC + c0);
        w4[i] = *reinterpret_cast<const float4*>(Wg + (size_t)(r0 + i * 64) * CC + c0);
    }
    #pragma unroll
    for (int i = 0; i < 2; i++) {
        int r = r0 + i * 64;
        uint32_t* pa = &As[0][r * BKP + c0];
        pa[0] = f2tf(a4[i].x); pa[1] = f2tf(a4[i].y);
        pa[2] = f2tf(a4[i].z); pa[3] = f2tf(a4[i].w);
        uint32_t* pw = &Ws[0][r * BKP + c0];
        pw[0] = f2tf(w4[i].x); pw[1] = f2tf(w4[i].y);
        pw[2] = f2tf(w4[i].z); pw[3] = f2tf(w4[i].w);
    }
    __syncthreads();

    for (int kt = 0; kt < NKT; kt++) {
        const int buf = kt & 1;
        if (kt < NKT - 1) {
            const int koff = (kt + 1) * GBK;
            #pragma unroll
            for (int i = 0; i < 2; i++) {
                a4[i] = *reinterpret_cast<const float4*>(
                    Ag + (size_t)(r0 + i * 64) * CC + koff + c0);
                w4[i] = *reinterpret_cast<const float4*>(
                    Wg + (size_t)(r0 + i * 64) * CC + koff + c0);
            }
        }

        #pragma unroll
        for (int ks = 0; ks < 2; ks++) {
            const int k0 = ks * 8;
            uint32_t af[4][4], bf[4][2];
            #pragma unroll
            for (int mt = 0; mt < 4; mt++) {
                const int row = warp_m * 64 + mt * 16 + g;
                const uint32_t* p  = &As[buf][row * BKP + k0 + tg];
                const uint32_t* p8 = p + 8 * BKP;
                af[mt][0] = p[0];
                af[mt][1] = p8[0];
                af[mt][2] = p[4];
                af[mt][3] = p8[4];
            }
            #pragma unroll
            for (int nt = 0; nt < 4; nt++) {
                const int rn = warp_n * 32 + nt * 8 + g;
                const uint32_t* p = &Ws[buf][rn * BKP + k0 + tg];
                bf[nt][0] = p[0];
                bf[nt][1] = p[4];
            }
            #pragma unroll
            for (int mt = 0; mt < 4; mt++)
                #pragma unroll
                for (int nt = 0; nt < 4; nt++)
                    mma_tf32(d[mt][nt], af[mt], bf[nt]);
        }

        if (kt < NKT - 1) {
            #pragma unroll
            for (int i = 0; i < 2; i++) {
                int r = r0 + i * 64;
                uint32_t* pa = &As[buf ^ 1][r * BKP + c0];
                pa[0] = f2tf(a4[i].x); pa[1] = f2tf(a4[i].y);
                pa[2] = f2tf(a4[i].z); pa[3] = f2tf(a4[i].w);
                uint32_t* pw = &Ws[buf ^ 1][r * BKP + c0];
                pw[0] = f2tf(w4[i].x); pw[1] = f2tf(w4[i].y);
                pw[2] = f2tf(w4[i].z); pw[3] = f2tf(w4[i].w);
            }
        }
        __syncthreads();
    }

    #pragma unroll
    for (int mt = 0; mt < 4; mt++) {
        const int row = m0 + warp_m * 64 + mt * 16 + g;
        #pragma unroll
        for (int nt = 0; nt < 4; nt++) {
            const int col = n0 + warp_n * 32 + nt * 8 + tg * 2;
            float2 bv = *reinterpret_cast<const float2*>(bias + col);
            float2 o0 = make_float2(d[mt][nt][0] + bv.x, d[mt][nt][1] + bv.y);
            float2 o1 = make_float2(d[mt][nt][2] + bv.x, d[mt][nt][3] + bv.y);
            *reinterpret_cast<float2*>(C + (size_t)row * CC + col) = o0;
            *reinterpret_cast<float2*>(C + (size_t)(row + 8) * CC + col) = o1;
        }
    }
}

// Single-matrix GEMM (output projection)
__global__ __launch_bounds__(256) void gemm_mma_kernel(
    const float* __restrict__ A, const float* __restrict__ W,
    const float* __restrict__ bias, float* __restrict__ C)
{
    __shared__ uint32_t As[2][128 * BKP];
    __shared__ uint32_t Ws[2][128 * BKP];
    gemm_mma_body(A, W, bias, C, blockIdx.y * 128, blockIdx.x * 128, As, Ws);
}

// Fused QKV projection: blockIdx.z selects {Wq,bq,q} / {Wk,bk,k} / {Wv,bv,v}
__global__ __launch_bounds__(256) void gemm_qkv_kernel(
    const float* __restrict__ x,
    const float* __restrict__ Wq, const float* __restrict__ bq, float* __restrict__ q,
    const float* __restrict__ Wk, const float* __restrict__ bk, float* __restrict__ k,
    const float* __restrict__ Wv, const float* __restrict__ bv, float* __restrict__ v)
{
    __shared__ uint32_t As[2][128 * BKP];
    __shared__ uint32_t Ws[2][128 * BKP];
    const float* W; const float* b; float* C;
    if (blockIdx.z == 0)      { W = Wq; b = bq; C = q; }
    else if (blockIdx.z == 1) { W = Wk; b = bk; C = k; }
    else                      { W = Wv; b = bv; C = v; }
    gemm_mma_body(x, W, b, C, blockIdx.y * 128, blockIdx.x * 128, As, Ws);
}

// ===========================================================================
// Tensor-core flash attention (causal), tf32 mma.sync.
// CTA: 128 q rows, 8 warps (16 q rows/warp), kv tile 64, D=64.
// grid = (T/128, H, B) = (16, 16, 2), 256 threads.
// qt REVERSED vs blockIdx.x so heaviest blocks schedule first.
// ===========================================================================
#define AQ 128
#define AKV 64
#define KP 68               // K/Q smem row pad (floats): bank = 4g+tg (bijective)
#define VP 72               // V   smem row pad (floats): bank = 8tg+g (bijective)
#define SM_K0 0
#define SM_K1 (64*KP)
#define SM_V0 (2*64*KP)
#define SM_V1 (2*64*KP + 64*VP)
#define ATT_SMEM_BYTES ((2*64*KP + 2*64*VP) * 4)   // 71680

__global__ __launch_bounds__(256, 2) void attention_mma_kernel(
    const float* __restrict__ Qg, const float* __restrict__ Kg,
    const float* __restrict__ Vg, float* __restrict__ Og)
{
    extern __shared__ __align__(16) float smf[];
    const uint32_t sbase = smem_u32(smf);
    const int tid = threadIdx.x;
    const int w = tid >> 5;
    const int lane = tid & 31;
    const int g = lane >> 2, tg = lane & 3;
    const int qt = gridDim.x - 1 - blockIdx.x;   // heavy blocks first
    const int h = blockIdx.y, b = blockIdx.z;
    const int q0 = qt * AQ;
    const size_t bh = (size_t)b * TT * CC + (size_t)h * DD;  // + t*CC + d

    // --- stage Q (scaled by 1/sqrt(D)) into smem [128][KP] ---
    {
        const float sc = 0.125f;
        #pragma unroll
        for (int j = 0; j < 8; j++) {
            int idx = tid + j * 256;           // 0..2047
            int r = idx >> 4, cc = (idx & 15) * 4;
            float4 val = *reinterpret_cast<const float4*>(
                Qg + bh + (size_t)(q0 + r) * CC + cc);
            float* dst = smf + r * KP + cc;
            dst[0] = val.x * sc; dst[1] = val.y * sc;
            dst[2] = val.z * sc; dst[3] = val.w * sc;
        }
    }
    __syncthreads();

    // --- Q A-fragments to registers (persist whole kernel) ---
    uint32_t qa[8][4];
    {
        const uint32_t* Qs = reinterpret_cast<const uint32_t*>(smf);
        const int r0 = (w * 16 + g) * KP;
        #pragma unroll
        for (int kk = 0; kk < 8; kk++) {
            qa[kk][0] = Qs[r0 + kk * 8 + tg];
            qa[kk][1] = Qs[r0 + 8 * KP + kk * 8 + tg];
            qa[kk][2] = Qs[r0 + kk * 8 + tg + 4];
            qa[kk][3] = Qs[r0 + 8 * KP + kk * 8 + tg + 4];
        }
    }
    __syncthreads();   // Q stage area becomes K buffers

    float s[8][4], oo[8][4];
    float m0 = -1e30f, m1 = -1e30f, l0 = 0.f, l1 = 0.f;
    #pragma unroll
    for (int nt = 0; nt < 8; nt++) {
        oo[nt][0] = oo[nt][1] = oo[nt][2] = oo[nt][3] = 0.f;
    }

    const int ntiles = 2 * qt + 2;
    const int wrow_first = q0 + w * 16;
    const int wrow_last  = wrow_first + 15;

    const uint32_t kbuf_b[2] = { sbase + SM_K0 * 4u, sbase + SM_K1 * 4u };
    const uint32_t vbuf_b[2] = { sbase + SM_V0 * 4u, sbase + SM_V1 * 4u };

    // preload tile 0
    #pragma unroll
    for (int j = 0; j < 4; j++) {
        int idx = tid + j * 256;               // 0..1023
        int r = idx >> 4, cc = (idx & 15) * 4;
        const float* srcK = Kg + bh + (size_t)r * CC + cc;
        const float* srcV = Vg + bh + (size_t)r * CC + cc;
        cp_async16(kbuf_b[0] + (uint32_t)(r * KP + cc) * 4u, srcK);
        cp_async16(vbuf_b[0] + (uint32_t)(r * VP + cc) * 4u, srcV);
    }
    asm volatile("cp.async.commit_group;");
    asm volatile("cp.async.wait_group 0;");
    __syncthreads();

    for (int t = 0; t < ntiles; t++) {
        const int buf = t & 1;
        if (t + 1 < ntiles) {
            const int kv0n = (t + 1) * AKV;
            #pragma unroll
            for (int j = 0; j < 4; j++) {
                int idx = tid + j * 256;
                int r = idx >> 4, cc = (idx & 15) * 4;
                const float* srcK = Kg + bh + (size_t)(kv0n + r) * CC + cc;
                const float* srcV = Vg + bh + (size_t)(kv0n + r) * CC + cc;
                cp_async16(kbuf_b[buf ^ 1] + (uint32_t)(r * KP + cc) * 4u, srcK);
                cp_async16(vbuf_b[buf ^ 1] + (uint32_t)(r * VP + cc) * 4u, srcV);
            }
            asm volatile("cp.async.commit_group;");
        }

        const int kv0 = t * AKV;
        if (kv0 <= wrow_last) {   // warp has at least one unmasked element
            const uint32_t* Ks = reinterpret_cast<const uint32_t*>(smf)
                                 + (buf ? SM_K1 : SM_K0);
            const uint32_t* Vs = reinterpret_cast<const uint32_t*>(smf)
                                 + (buf ? SM_V1 : SM_V0);
            // ---- S = Q K^T ----
            #pragma unroll
            for (int nt = 0; nt < 8; nt++) {
                s[nt][0] = s[nt][1] = s[nt][2] = s[nt][3] = 0.f;
            }
            #pragma unroll
            for (int nt = 0; nt < 8; nt++) {
                const int rb = (nt * 8 + g) * KP;
                #pragma unroll
                for (int kk = 0; kk < 8; kk++) {
                    uint32_t bb[2] = { Ks[rb + kk * 8 + tg], Ks[rb + kk * 8 + tg + 4] };
                    mma_tf32(s[nt], qa[kk], bb);
                }
            }
            // ---- causal mask (diagonal tiles only) ----
            if (kv0 + AKV - 1 > wrow_first) {
                const int r0a = wrow_first + g, r1a = r0a + 8;
                #pragma unroll
                for (int nt = 0; nt < 8; nt++) {
                    const int c = kv0 + nt * 8 + 2 * tg;
                    if (c     > r0a) s[nt][0] = -1e30f;
                    if (c + 1 > r0a) s[nt][1] = -1e30f;
                    if (c     > r1a) s[nt][2] = -1e30f;
                    if (c + 1 > r1a) s[nt][3] = -1e30f;
                }
            }
            // ---- online softmax (register-resident) ----
            float mx0 = m0, mx1 = m1;
            #pragma unroll
            for (int nt = 0; nt < 8; nt++) {
                mx0 = fmaxf(mx0, fmaxf(s[nt][0], s[nt][1]));
                mx1 = fmaxf(mx1, fmaxf(s[nt][2], s[nt][3]));
            }
            mx0 = fmaxf(mx0, __shfl_xor_sync(0xffffffffu, mx0, 1));
            mx0 = fmaxf(mx0, __shfl_xor_sync(0xffffffffu, mx0, 2));
            mx1 = fmaxf(mx1, __shfl_xor_sync(0xffffffffu, mx1, 1));
            mx1 = fmaxf(mx1, __shfl_xor_sync(0xffffffffu, mx1, 2));
            const float al0 = __expf(m0 - mx0), al1 = __expf(m1 - mx1);
            m0 = mx0; m1 = mx1;
            float sum0 = 0.f, sum1 = 0.f;
            #pragma unroll
            for (int nt = 0; nt < 8; nt++) {
                s[nt][0] = __expf(s[nt][0] - mx0); sum0 += s[nt][0];
                s[nt][1] = __expf(s[nt][1] - mx0); sum0 += s[nt][1];
                s[nt][2] = __expf(s[nt][2] - mx1); sum1 += s[nt][2];
                s[nt][3] = __expf(s[nt][3] - mx1); sum1 += s[nt][3];
            }
            l0 = l0 * al0 + sum0;
            l1 = l1 * al1 + sum1;
            #pragma unroll
            for (int nt = 0; nt < 8; nt++) {
                oo[nt][0] *= al0; oo[nt][1] *= al0;
                oo[nt][2] *= al1; oo[nt][3] *= al1;
            }
            // ---- P (C-frag) -> A-frag via shuffles, in place ----
            const int base = lane & ~3;
            #pragma unroll
            for (int kk = 0; kk < 8; kk++) {
                const int srcA = base | (tg >> 1);
                const int srcB = srcA + 2;
                float x0 = __shfl_sync(0xffffffffu, s[kk][0], srcA);
                float x1 = __shfl_sync(0xffffffffu, s[kk][1], srcA);
                float x2 = __shfl_sync(0xffffffffu, s[kk][2], srcA);
                float x3 = __shfl_sync(0xffffffffu, s[kk][3], srcA);
                float y0 = __shfl_sync(0xffffffffu, s[kk][0], srcB);
                float y1 = __shfl_sync(0xffffffffu, s[kk][1], srcB);
                float y2 = __shfl_sync(0xffffffffu, s[kk][2], srcB);
                float y3 = __shfl_sync(0xffffffffu, s[kk][3], srcB);
                const bool odd = tg & 1;
                s[kk][0] = odd ? x1 : x0;   // a0: row g,   col tg
                s[kk][1] = odd ? x3 : x2;   // a1: row g+8, col tg
                s[kk][2] = odd ? y1 : y0;   // a2: row g,   col tg+4
                s[kk][3] = odd ? y3 : y2;   // a3: row g+8, col tg+4
            }
            // ---- O += P V ----
            #pragma unroll
            for (int nt = 0; nt < 8; nt++) {
                #pragma unroll
                for (int kk = 0; kk < 8; kk++) {
                    uint32_t bb[2] = { Vs[(kk * 8 + tg) * VP + nt * 8 + g],
                                       Vs[(kk * 8 + tg + 4) * VP + nt * 8 + g] };
                    mma_tf32(oo[nt], reinterpret_cast<uint32_t*>(s[kk]), bb);
                }
            }
        }
        if (t + 1 < ntiles) asm volatile("cp.async.wait_group 0;");
        __syncthreads();
    }

    // ---- finalize: reduce l over the quad, normalize, store ----
    l0 += __shfl_xor_sync(0xffffffffu, l0, 1);
    l0 += __shfl_xor_sync(0xffffffffu, l0, 2);
    l1 += __shfl_xor_sync(0xffffffffu, l1, 1);
    l1 += __shfl_xor_sync(0xffffffffu, l1, 2);
    const float inv0 = 1.f / l0, inv1 = 1.f / l1;
    const int r0a = q0 + w * 16 + g, r1a = r0a + 8;
    #pragma unroll
    for (int nt = 0; nt < 8; nt++) {
        const int c = nt * 8 + 2 * tg;
        *reinterpret_cast<float2*>(Og + bh + (size_t)r0a * CC + c) =
            make_float2(oo[nt][0] * inv0, oo[nt][1] * inv0);
        *reinterpret_cast<float2*>(Og + bh + (size_t)r1a * CC + c) =
            make_float2(oo[nt][2] * inv1, oo[nt][3] * inv1);
    }
}

// ---------------------------------------------------------------------------
// Launch
// ---------------------------------------------------------------------------
extern "C" void kernel_launch(void* const* d_in, const int* in_sizes, int n_in,
                              void* d_out, int out_size)
{
    const float* x  = (const float*)d_in[0];
    const float* Wq = (const float*)d_in[1];
    const float* bq = (const float*)d_in[2];
    const float* Wk = (const float*)d_in[3];
    const float* bk = (const float*)d_in[4];
    const float* Wv = (const float*)d_in[5];
    const float* bv = (const float*)d_in[6];
    const float* Wo = (const float*)d_in[7];
    const float* bo = (const float*)d_in[8];
    float* out = (float*)d_out;

    float *qp, *kp, *vp, *ap;
    cudaGetSymbolAddress((void**)&qp, g_q);
    cudaGetSymbolAddress((void**)&kp, g_k);
    cudaGetSymbolAddress((void**)&vp, g_v);
    cudaGetSymbolAddress((void**)&ap, g_att);

    // Fused QKV projection: one launch, 768 CTAs
    gemm_qkv_kernel<<<dim3(CC / 128, MM / 128, 3), 256>>>(
        x, Wq, bq, qp, Wk, bk, kp, Wv, bv, vp);

    cudaFuncSetAttribute(attention_mma_kernel,
                         cudaFuncAttributeMaxDynamicSharedMemorySize,
                         ATT_SMEM_BYTES);
    attention_mma_kernel<<<dim3(TT / AQ, HH, BB), 256, ATT_SMEM_BYTES>>>(
        qp, kp, vp, ap);

    gemm_mma_kernel<<<dim3(CC / 128, MM / 128), 256>>>(ap, Wo, bo, out);
}

// round 8
// speedup vs baseline: 3.2874x; 1.0570x over previous
#include <cuda_runtime.h>
#include <cuda_bf16.h>
#include <math.h>
#include <cstdint>

// Problem constants
#define BB 2
#define TT 2048
#define CC 1024
#define HH 16
#define DD 64
#define MM (BB*TT)   // 4096

// ---------------------------------------------------------------------------
// Scratch (allocation-free: __device__ globals)
// ---------------------------------------------------------------------------
__device__ float g_q[MM*CC];
__device__ float g_k[MM*CC];
__device__ float g_v[MM*CC];
__device__ float g_att[MM*CC];

// ---------------------------------------------------------------------------
// mma.sync helpers (sm_100 base target: HMMA path, no tcgen05)
// ---------------------------------------------------------------------------
__device__ __forceinline__ uint32_t f2tf(float f) {
    uint32_t u;
    asm("cvt.rna.tf32.f32 %0, %1;" : "=r"(u) : "f"(f));
    return u;
}

__device__ __forceinline__ void mma_tf32(float* d, const uint32_t* a, const uint32_t* b) {
    asm volatile(
        "mma.sync.aligned.m16n8k8.row.col.f32.tf32.tf32.f32 "
        "{%0,%1,%2,%3}, {%4,%5,%6,%7}, {%8,%9}, {%0,%1,%2,%3};"
        : "+f"(d[0]), "+f"(d[1]), "+f"(d[2]), "+f"(d[3])
        : "r"(a[0]), "r"(a[1]), "r"(a[2]), "r"(a[3]),
          "r"(b[0]), "r"(b[1]));
}

__device__ __forceinline__ uint32_t smem_u32(const void* p) {
    uint32_t a;
    asm("{ .reg .u64 t; cvta.to.shared.u64 t, %1; cvt.u32.u64 %0, t; }"
        : "=r"(a) : "l"(p));
    return a;
}

__device__ __forceinline__ void cp_async16(uint32_t dst, const void* src) {
    asm volatile("cp.async.ca.shared.global [%0], [%1], 16;" :: "r"(dst), "l"(src));
}

__device__ __forceinline__ void cp_async16_cg(uint32_t dst, const void* src) {
    asm volatile("cp.async.cg.shared.global [%0], [%1], 16;" :: "r"(dst), "l"(src));
}

// ===========================================================================
// tf32 mma.sync GEMM core:  C[M,N] = A[M,K] @ W[N,K]^T + bias[N]
// CTA tile 128x128, BK=16, 256 threads = 8 warps (2M x 4N), warp tile 64x32.
// cp.async staging of RAW fp32; cvt.rna.tf32 applied at fragment load
// (bit-identical to converting at store time). One __syncthreads per k-tile,
// gmem wait at loop top so prefetch overlaps the whole MMA block.
// ===========================================================================
#define GBK 16
#define BKP 20
#define NKT (CC / GBK)      // 64

__device__ __forceinline__ void gemm_mma_body(
    const float* __restrict__ A, const float* __restrict__ W,
    const float* __restrict__ bias, float* __restrict__ C,
    int m0, int n0,
    uint32_t (*As)[128 * BKP], uint32_t (*Ws)[128 * BKP])
{
    const int tid = threadIdx.x;
    const int wid = tid >> 5;
    const int lane = tid & 31;
    const int g  = lane >> 2;
    const int tg = lane & 3;
    const int warp_m = wid >> 2;
    const int warp_n = wid & 3;
    const float* Ag = A + (size_t)m0 * CC;
    const float* Wg = W + (size_t)n0 * CC;

    const uint32_t sA[2] = { smem_u32(As[0]), smem_u32(As[1]) };
    const uint32_t sW[2] = { smem_u32(Ws[0]), smem_u32(Ws[1]) };

    float d[4][4][4];
    #pragma unroll
    for (int mt = 0; mt < 4; mt++)
        #pragma unroll
        for (int nt = 0; nt < 4; nt++)
            #pragma unroll
            for (int r = 0; r < 4; r++) d[mt][nt][r] = 0.f;

    const int r0 = tid >> 2;          // 0..63 : rows r0 and r0+64
    const int c0 = (tid & 3) * 4;     // 0,4,8,12

    // preload kt = 0 into buffer 0
    #pragma unroll
    for (int i = 0; i < 2; i++) {
        const int r = r0 + i * 64;
        const uint32_t so = (uint32_t)(r * BKP + c0) * 4u;
        cp_async16_cg(sA[0] + so, Ag + (size_t)r * CC + c0);
        cp_async16_cg(sW[0] + so, Wg + (size_t)r * CC + c0);
    }
    asm volatile("cp.async.commit_group;");

    for (int kt = 0; kt < NKT; kt++) {
        const int buf = kt & 1;
        asm volatile("cp.async.wait_group 0;");
        __syncthreads();   // buf data visible to all; compute(kt-1) readers done

        if (kt < NKT - 1) {
            const int koff = (kt + 1) * GBK;
            #pragma unroll
            for (int i = 0; i < 2; i++) {
                const int r = r0 + i * 64;
                const uint32_t so = (uint32_t)(r * BKP + c0) * 4u;
                cp_async16_cg(sA[buf ^ 1] + so, Ag + (size_t)r * CC + koff + c0);
                cp_async16_cg(sW[buf ^ 1] + so, Wg + (size_t)r * CC + koff + c0);
            }
            asm volatile("cp.async.commit_group;");
        }

        // compute on current buffer: 2 k-steps of k=8
        #pragma unroll
        for (int ks = 0; ks < 2; ks++) {
            const int k0 = ks * 8;
            uint32_t af[4][4], bf[4][2];
            #pragma unroll
            for (int mt = 0; mt < 4; mt++) {
                const int row = warp_m * 64 + mt * 16 + g;
                const uint32_t* p  = &As[buf][row * BKP + k0 + tg];
                const uint32_t* p8 = p + 8 * BKP;
                af[mt][0] = f2tf(__uint_as_float(p[0]));
                af[mt][1] = f2tf(__uint_as_float(p8[0]));
                af[mt][2] = f2tf(__uint_as_float(p[4]));
                af[mt][3] = f2tf(__uint_as_float(p8[4]));
            }
            #pragma unroll
            for (int nt = 0; nt < 4; nt++) {
                const int rn = warp_n * 32 + nt * 8 + g;
                const uint32_t* p = &Ws[buf][rn * BKP + k0 + tg];
                bf[nt][0] = f2tf(__uint_as_float(p[0]));
                bf[nt][1] = f2tf(__uint_as_float(p[4]));
            }
            #pragma unroll
            for (int mt = 0; mt < 4; mt++)
                #pragma unroll
                for (int nt = 0; nt < 4; nt++)
                    mma_tf32(d[mt][nt], af[mt], bf[nt]);
        }
        // no bottom sync: top-of-loop sync separates readers from prefetch writers
    }

    #pragma unroll
    for (int mt = 0; mt < 4; mt++) {
        const int row = m0 + warp_m * 64 + mt * 16 + g;
        #pragma unroll
        for (int nt = 0; nt < 4; nt++) {
            const int col = n0 + warp_n * 32 + nt * 8 + tg * 2;
            float2 bv = *reinterpret_cast<const float2*>(bias + col);
            float2 o0 = make_float2(d[mt][nt][0] + bv.x, d[mt][nt][1] + bv.y);
            float2 o1 = make_float2(d[mt][nt][2] + bv.x, d[mt][nt][3] + bv.y);
            *reinterpret_cast<float2*>(C + (size_t)row * CC + col) = o0;
            *reinterpret_cast<float2*>(C + (size_t)(row + 8) * CC + col) = o1;
        }
    }
}

// Single-matrix GEMM (output projection)
__global__ __launch_bounds__(256) void gemm_mma_kernel(
    const float* __restrict__ A, const float* __restrict__ W,
    const float* __restrict__ bias, float* __restrict__ C)
{
    __shared__ uint32_t As[2][128 * BKP];
    __shared__ uint32_t Ws[2][128 * BKP];
    gemm_mma_body(A, W, bias, C, blockIdx.y * 128, blockIdx.x * 128, As, Ws);
}

// Fused QKV projection: blockIdx.z selects {Wq,bq,q} / {Wk,bk,k} / {Wv,bv,v}
__global__ __launch_bounds__(256) void gemm_qkv_kernel(
    const float* __restrict__ x,
    const float* __restrict__ Wq, const float* __restrict__ bq, float* __restrict__ q,
    const float* __restrict__ Wk, const float* __restrict__ bk, float* __restrict__ k,
    const float* __restrict__ Wv, const float* __restrict__ bv, float* __restrict__ v)
{
    __shared__ uint32_t As[2][128 * BKP];
    __shared__ uint32_t Ws[2][128 * BKP];
    const float* W; const float* b; float* C;
    if (blockIdx.z == 0)      { W = Wq; b = bq; C = q; }
    else if (blockIdx.z == 1) { W = Wk; b = bk; C = k; }
    else                      { W = Wv; b = bv; C = v; }
    gemm_mma_body(x, W, b, C, blockIdx.y * 128, blockIdx.x * 128, As, Ws);
}

// ===========================================================================
// Tensor-core flash attention (causal), tf32 mma.sync.   (unchanged R6/R7)
// CTA: 128 q rows, 8 warps (16 q rows/warp), kv tile 64, D=64.
// grid = (T/128, H, B) = (16, 16, 2), 256 threads.
// qt REVERSED vs blockIdx.x so heaviest blocks schedule first.
// ===========================================================================
#define AQ 128
#define AKV 64
#define KP 68               // K/Q smem row pad (floats): bank = 4g+tg (bijective)
#define VP 72               // V   smem row pad (floats): bank = 8tg+g (bijective)
#define SM_K0 0
#define SM_K1 (64*KP)
#define SM_V0 (2*64*KP)
#define SM_V1 (2*64*KP + 64*VP)
#define ATT_SMEM_BYTES ((2*64*KP + 2*64*VP) * 4)   // 71680

__global__ __launch_bounds__(256, 2) void attention_mma_kernel(
    const float* __restrict__ Qg, const float* __restrict__ Kg,
    const float* __restrict__ Vg, float* __restrict__ Og)
{
    extern __shared__ __align__(16) float smf[];
    const uint32_t sbase = smem_u32(smf);
    const int tid = threadIdx.x;
    const int w = tid >> 5;
    const int lane = tid & 31;
    const int g = lane >> 2, tg = lane & 3;
    const int qt = gridDim.x - 1 - blockIdx.x;   // heavy blocks first
    const int h = blockIdx.y, b = blockIdx.z;
    const int q0 = qt * AQ;
    const size_t bh = (size_t)b * TT * CC + (size_t)h * DD;  // + t*CC + d

    // --- stage Q (scaled by 1/sqrt(D)) into smem [128][KP] ---
    {
        const float sc = 0.125f;
        #pragma unroll
        for (int j = 0; j < 8; j++) {
            int idx = tid + j * 256;           // 0..2047
            int r = idx >> 4, cc = (idx & 15) * 4;
            float4 val = *reinterpret_cast<const float4*>(
                Qg + bh + (size_t)(q0 + r) * CC + cc);
            float* dst = smf + r * KP + cc;
            dst[0] = val.x * sc; dst[1] = val.y * sc;
            dst[2] = val.z * sc; dst[3] = val.w * sc;
        }
    }
    __syncthreads();

    // --- Q A-fragments to registers (persist whole kernel) ---
    uint32_t qa[8][4];
    {
        const uint32_t* Qs = reinterpret_cast<const uint32_t*>(smf);
        const int r0 = (w * 16 + g) * KP;
        #pragma unroll
        for (int kk = 0; kk < 8; kk++) {
            qa[kk][0] = Qs[r0 + kk * 8 + tg];
            qa[kk][1] = Qs[r0 + 8 * KP + kk * 8 + tg];
            qa[kk][2] = Qs[r0 + kk * 8 + tg + 4];
            qa[kk][3] = Qs[r0 + 8 * KP + kk * 8 + tg + 4];
        }
    }
    __syncthreads();   // Q stage area becomes K buffers

    float s[8][4], oo[8][4];
    float m0 = -1e30f, m1 = -1e30f, l0 = 0.f, l1 = 0.f;
    #pragma unroll
    for (int nt = 0; nt < 8; nt++) {
        oo[nt][0] = oo[nt][1] = oo[nt][2] = oo[nt][3] = 0.f;
    }

    const int ntiles = 2 * qt + 2;
    const int wrow_first = q0 + w * 16;
    const int wrow_last  = wrow_first + 15;

    const uint32_t kbuf_b[2] = { sbase + SM_K0 * 4u, sbase + SM_K1 * 4u };
    const uint32_t vbuf_b[2] = { sbase + SM_V0 * 4u, sbase + SM_V1 * 4u };

    // preload tile 0
    #pragma unroll
    for (int j = 0; j < 4; j++) {
        int idx = tid + j * 256;               // 0..1023
        int r = idx >> 4, cc = (idx & 15) * 4;
        const float* srcK = Kg + bh + (size_t)r * CC + cc;
        const float* srcV = Vg + bh + (size_t)r * CC + cc;
        cp_async16(kbuf_b[0] + (uint32_t)(r * KP + cc) * 4u, srcK);
        cp_async16(vbuf_b[0] + (uint32_t)(r * VP + cc) * 4u, srcV);
    }
    asm volatile("cp.async.commit_group;");
    asm volatile("cp.async.wait_group 0;");
    __syncthreads();

    for (int t = 0; t < ntiles; t++) {
        const int buf = t & 1;
        if (t + 1 < ntiles) {
            const int kv0n = (t + 1) * AKV;
            #pragma unroll
            for (int j = 0; j < 4; j++) {
                int idx = tid + j * 256;
                int r = idx >> 4, cc = (idx & 15) * 4;
                const float* srcK = Kg + bh + (size_t)(kv0n + r) * CC + cc;
                const float* srcV = Vg + bh + (size_t)(kv0n + r) * CC + cc;
                cp_async16(kbuf_b[buf ^ 1] + (uint32_t)(r * KP + cc) * 4u, srcK);
                cp_async16(vbuf_b[buf ^ 1] + (uint32_t)(r * VP + cc) * 4u, srcV);
            }
            asm volatile("cp.async.commit_group;");
        }

        const int kv0 = t * AKV;
        if (kv0 <= wrow_last) {   // warp has at least one unmasked element
            const uint32_t* Ks = reinterpret_cast<const uint32_t*>(smf)
                                 + (buf ? SM_K1 : SM_K0);
            const uint32_t* Vs = reinterpret_cast<const uint32_t*>(smf)
                                 + (buf ? SM_V1 : SM_V0);
            // ---- S = Q K^T ----
            #pragma unroll
            for (int nt = 0; nt < 8; nt++) {
                s[nt][0] = s[nt][1] = s[nt][2] = s[nt][3] = 0.f;
            }
            #pragma unroll
            for (int nt = 0; nt < 8; nt++) {
                const int rb = (nt * 8 + g) * KP;
                #pragma unroll
                for (int kk = 0; kk < 8; kk++) {
                    uint32_t bb[2] = { Ks[rb + kk * 8 + tg], Ks[rb + kk * 8 + tg + 4] };
                    mma_tf32(s[nt], qa[kk], bb);
                }
            }
            // ---- causal mask (diagonal tiles only) ----
            if (kv0 + AKV - 1 > wrow_first) {
                const int r0a = wrow_first + g, r1a = r0a + 8;
                #pragma unroll
                for (int nt = 0; nt < 8; nt++) {
                    const int c = kv0 + nt * 8 + 2 * tg;
                    if (c     > r0a) s[nt][0] = -1e30f;
                    if (c + 1 > r0a) s[nt][1] = -1e30f;
                    if (c     > r1a) s[nt][2] = -1e30f;
                    if (c + 1 > r1a) s[nt][3] = -1e30f;
                }
            }
            // ---- online softmax (register-resident) ----
            float mx0 = m0, mx1 = m1;
            #pragma unroll
            for (int nt = 0; nt < 8; nt++) {
                mx0 = fmaxf(mx0, fmaxf(s[nt][0], s[nt][1]));
                mx1 = fmaxf(mx1, fmaxf(s[nt][2], s[nt][3]));
            }
            mx0 = fmaxf(mx0, __shfl_xor_sync(0xffffffffu, mx0, 1));
            mx0 = fmaxf(mx0, __shfl_xor_sync(0xffffffffu, mx0, 2));
            mx1 = fmaxf(mx1, __shfl_xor_sync(0xffffffffu, mx1, 1));
            mx1 = fmaxf(mx1, __shfl_xor_sync(0xffffffffu, mx1, 2));
            const float al0 = __expf(m0 - mx0), al1 = __expf(m1 - mx1);
            m0 = mx0; m1 = mx1;
            float sum0 = 0.f, sum1 = 0.f;
            #pragma unroll
            for (int nt = 0; nt < 8; nt++) {
                s[nt][0] = __expf(s[nt][0] - mx0); sum0 += s[nt][0];
                s[nt][1] = __expf(s[nt][1] - mx0); sum0 += s[nt][1];
                s[nt][2] = __expf(s[nt][2] - mx1); sum1 += s[nt][2];
                s[nt][3] = __expf(s[nt][3] - mx1); sum1 += s[nt][3];
            }
            l0 = l0 * al0 + sum0;
            l1 = l1 * al1 + sum1;
            #pragma unroll
            for (int nt = 0; nt < 8; nt++) {
                oo[nt][0] *= al0; oo[nt][1] *= al0;
                oo[nt][2] *= al1; oo[nt][3] *= al1;
            }
            // ---- P (C-frag) -> A-frag via shuffles, in place ----
            const int base = lane & ~3;
            #pragma unroll
            for (int kk = 0; kk < 8; kk++) {
                const int srcA = base | (tg >> 1);
                const int srcB = srcA + 2;
                float x0 = __shfl_sync(0xffffffffu, s[kk][0], srcA);
                float x1 = __shfl_sync(0xffffffffu, s[kk][1], srcA);
                float x2 = __shfl_sync(0xffffffffu, s[kk][2], srcA);
                float x3 = __shfl_sync(0xffffffffu, s[kk][3], srcA);
                float y0 = __shfl_sync(0xffffffffu, s[kk][0], srcB);
                float y1 = __shfl_sync(0xffffffffu, s[kk][1], srcB);
                float y2 = __shfl_sync(0xffffffffu, s[kk][2], srcB);
                float y3 = __shfl_sync(0xffffffffu, s[kk][3], srcB);
                const bool odd = tg & 1;
                s[kk][0] = odd ? x1 : x0;   // a0: row g,   col tg
                s[kk][1] = odd ? x3 : x2;   // a1: row g+8, col tg
                s[kk][2] = odd ? y1 : y0;   // a2: row g,   col tg+4
                s[kk][3] = odd ? y3 : y2;   // a3: row g+8, col tg+4
            }
            // ---- O += P V ----
            #pragma unroll
            for (int nt = 0; nt < 8; nt++) {
                #pragma unroll
                for (int kk = 0; kk < 8; kk++) {
                    uint32_t bb[2] = { Vs[(kk * 8 + tg) * VP + nt * 8 + g],
                                       Vs[(kk * 8 + tg + 4) * VP + nt * 8 + g] };
                    mma_tf32(oo[nt], reinterpret_cast<uint32_t*>(s[kk]), bb);
                }
            }
        }
        if (t + 1 < ntiles) asm volatile("cp.async.wait_group 0;");
        __syncthreads();
    }

    // ---- finalize: reduce l over the quad, normalize, store ----
    l0 += __shfl_xor_sync(0xffffffffu, l0, 1);
    l0 += __shfl_xor_sync(0xffffffffu, l0, 2);
    l1 += __shfl_xor_sync(0xffffffffu, l1, 1);
    l1 += __shfl_xor_sync(0xffffffffu, l1, 2);
    const float inv0 = 1.f / l0, inv1 = 1.f / l1;
    const int r0a = q0 + w * 16 + g, r1a = r0a + 8;
    #pragma unroll
    for (int nt = 0; nt < 8; nt++) {
        const int c = nt * 8 + 2 * tg;
        *reinterpret_cast<float2*>(Og + bh + (size_t)r0a * CC + c) =
            make_float2(oo[nt][0] * inv0, oo[nt][1] * inv0);
        *reinterpret_cast<float2*>(Og + bh + (size_t)r1a * CC + c) =
            make_float2(oo[nt][2] * inv1, oo[nt][3] * inv1);
    }
}

// ---------------------------------------------------------------------------
// Launch
// ---------------------------------------------------------------------------
extern "C" void kernel_launch(void* const* d_in, const int* in_sizes, int n_in,
                              void* d_out, int out_size)
{
    const float* x  = (const float*)d_in[0];
    const float* Wq = (const float*)d_in[1];
    const float* bq = (const float*)d_in[2];
    const float* Wk = (const float*)d_in[3];
    const float* bk = (const float*)d_in[4];
    const float* Wv = (const float*)d_in[5];
    const float* bv = (const float*)d_in[6];
    const float* Wo = (const float*)d_in[7];
    const float* bo = (const float*)d_in[8];
    float* out = (float*)d_out;

    float *qp, *kp, *vp, *ap;
    cudaGetSymbolAddress((void**)&qp, g_q);
    cudaGetSymbolAddress((void**)&kp, g_k);
    cudaGetSymbolAddress((void**)&vp, g_v);
    cudaGetSymbolAddress((void**)&ap, g_att);

    // Fused QKV projection: one launch, 768 CTAs
    gemm_qkv_kernel<<<dim3(CC / 128, MM / 128, 3), 256>>>(
        x, Wq, bq, qp, Wk, bk, kp, Wv, bv, vp);

    cudaFuncSetAttribute(attention_mma_kernel,
                         cudaFuncAttributeMaxDynamicSharedMemorySize,
                         ATT_SMEM_BYTES);
    attention_mma_kernel<<<dim3(TT / AQ, HH, BB), 256, ATT_SMEM_BYTES>>>(
        qp, kp, vp, ap);

    gemm_mma_kernel<<<dim3(CC / 128, MM / 128), 256>>>(ap, Wo, bo, out);
}